// round 16
// baseline (speedup 1.0000x reference)
#include <cuda_runtime.h>
#include <math.h>

#define EPSF 1e-5f
#define NW 12            // warps per CTA
#define NITER 24         // 288 / NW

// Duplicated-broadcast weights for i-axis packing:
// W2_buf[((B*8 + m)*32 + C)*2 + e] = {w, w}, w = W[B][C][jk], jk = 2m+e,
// m = j*2 + (k>>1). ulonglong2 view: element (B,m,C) = {dup(w_jk_even), dup(w_jk_odd)}.
__device__ float2 W2_buf[288 * 16 * 32];

__global__ void transpose_W_kernel(const float* __restrict__ Wg) {
    int idx = blockIdx.x * 256 + threadIdx.x;   // one u64 (float2) per thread
    if (idx >= 288 * 16 * 32) return;
    int e = idx & 1;
    int C = (idx >> 1) & 31;
    int m = (idx >> 6) & 7;
    int B = idx >> 9;
    int jk = m * 2 + e;
    float w = Wg[((B << 5) + C) * 16 + jk];
    W2_buf[idx] = make_float2(w, w);
}

typedef unsigned long long u64;

#define PACK2(d, s)      asm("mov.b64 %0, {%1, %1};" : "=l"(d) : "f"(s))
#define UNPK2(lo, hi, s) asm("mov.b64 {%0, %1}, %2;" : "=f"(lo), "=f"(hi) : "l"(s))
#define FMA2(d, a, b, c) asm("fma.rn.f32x2 %0, %1, %2, %3;" : "=l"(d) : "l"(a), "l"(b), "l"(c))
#define MUL2(d, a, b)    asm("mul.rn.f32x2 %0, %1, %2;" : "=l"(d) : "l"(a), "l"(b))
#define ADD2(d, a, b)    asm("add.rn.f32x2 %0, %1, %2;" : "=l"(d) : "l"(a), "l"(b))

// SMEM layout (floats) — TWO positions per CTA, 12 warps.
// Xs stored TRANSPOSED per B: Xt[B][j][i] (j outer), so i-pairs are contiguous.
//  Xs0  [288*16]        = 4608   @0
//  Xs1  [288*16]        = 4608   @4608
//  vbuf [2][12*32*16]   = 12288  @9216
//  vcur [2][32*16]      = 1024   @21504
//  invd [2][32]         = 64     @22528
//  mred [2][12*32]      = 768    @22592
//  nred [2][12*32]      = 768    @23360
#define SMEM_FLOATS 24128

// p_out has 4*32*16*8*8 = 131072 elements; a_out follows it.
#define AOUT_BASE 131072

// Load duplicated W for B: 8 LDG.128, fills w00..w33 (w_jk).
#define LOADW2(B)                                                              \
    {                                                                          \
        const ulonglong2* Wp_ = W2v + ((B) << 8) + lane;                       \
        ulonglong2 t0 = Wp_[0],   t1 = Wp_[32],  t2 = Wp_[64],  t3 = Wp_[96];  \
        ulonglong2 t4 = Wp_[128], t5 = Wp_[160], t6 = Wp_[192], t7 = Wp_[224]; \
        w00 = t0.x; w01 = t0.y; w02 = t1.x; w03 = t1.y;                        \
        w10 = t2.x; w11 = t2.y; w12 = t3.x; w13 = t3.y;                        \
        w20 = t4.x; w21 = t4.y; w22 = t5.x; w23 = t5.y;                        \
        w30 = t6.x; w31 = t6.y; w32 = t7.x; w33 = t7.y;                        \
    }

// i-packed u: ue_k = {u[0][k],u[1][k]}, uo_k = {u[2][k],u[3][k]}.
// X pairs loaded directly (no packing): Xp[j] = { {X0j,X1j}, {X2j,X3j} }.
#define COMPUTE_U_I(XV2, B, ue0, uo0, ue1, uo1, ue2, uo2, ue3, uo3)            \
    {                                                                          \
        const ulonglong2* Xp = (XV2) + ((B) << 2);                             \
        ulonglong2 x0 = Xp[0], x1 = Xp[1], x2 = Xp[2], x3 = Xp[3];             \
        MUL2(ue0, x0.x, w00);       MUL2(uo0, x0.y, w00);                      \
        FMA2(ue0, x1.x, w10, ue0);  FMA2(uo0, x1.y, w10, uo0);                 \
        FMA2(ue0, x2.x, w20, ue0);  FMA2(uo0, x2.y, w20, uo0);                 \
        FMA2(ue0, x3.x, w30, ue0);  FMA2(uo0, x3.y, w30, uo0);                 \
        MUL2(ue1, x0.x, w01);       MUL2(uo1, x0.y, w01);                      \
        FMA2(ue1, x1.x, w11, ue1);  FMA2(uo1, x1.y, w11, uo1);                 \
        FMA2(ue1, x2.x, w21, ue1);  FMA2(uo1, x2.y, w21, uo1);                 \
        FMA2(ue1, x3.x, w31, ue1);  FMA2(uo1, x3.y, w31, uo1);                 \
        MUL2(ue2, x0.x, w02);       MUL2(uo2, x0.y, w02);                      \
        FMA2(ue2, x1.x, w12, ue2);  FMA2(uo2, x1.y, w12, uo2);                 \
        FMA2(ue2, x2.x, w22, ue2);  FMA2(uo2, x2.y, w22, uo2);                 \
        FMA2(ue2, x3.x, w32, ue2);  FMA2(uo2, x3.y, w32, uo2);                 \
        MUL2(ue3, x0.x, w03);       MUL2(uo3, x0.y, w03);                      \
        FMA2(ue3, x1.x, w13, ue3);  FMA2(uo3, x1.y, w13, uo3);                 \
        FMA2(ue3, x2.x, w23, ue3);  FMA2(uo3, x2.y, w23, uo3);                 \
        FMA2(ue3, x3.x, w33, ue3);  FMA2(uo3, x3.y, w33, uo3);                 \
    }

// packed elementwise dot of 8 pairs -> scalar (lo+hi)
#define PDOT8(res, ua0, ub0, ua1, ub1, ua2, ub2, ua3, ub3,                     \
              va0, vb0, va1, vb1, va2, vb2, va3, vb3)                          \
    {                                                                          \
        u64 t_;                                                                \
        MUL2(t_, ua0, va0); FMA2(t_, ub0, vb0, t_);                            \
        FMA2(t_, ua1, va1, t_); FMA2(t_, ub1, vb1, t_);                        \
        FMA2(t_, ua2, va2, t_); FMA2(t_, ub2, vb2, t_);                        \
        FMA2(t_, ua3, va3, t_); FMA2(t_, ub3, vb3, t_);                        \
        float lo_, hi_;                                                        \
        UNPK2(lo_, hi_, t_);                                                   \
        res = lo_ + hi_;                                                       \
    }

__global__ __launch_bounds__(384, 1)
void convcaps_kernel(const float* __restrict__ x,
                     float* __restrict__ out) {
    extern __shared__ float smem[];
    float* Xs0  = smem;
    float* Xs1  = smem + 4608;
    float* vbuf = smem + 9216;
    float* vcur = smem + 21504;
    float* invd = smem + 22528;
    float* mred = smem + 22592;
    float* nred = smem + 23360;

    const int tid  = threadIdx.x;
    const int lane = tid & 31;       // = C
    const int wp   = tid >> 5;       // warp id 0..11, B ≡ wp (mod 12)
    const int pos0 = blockIdx.x * 2; // two positions per CTA

    const ulonglong2* W2v = reinterpret_cast<const ulonglong2*>(W2_buf);

    // ---- gather patch poses for BOTH positions, TRANSPOSED (j outer) ----
    for (int idx = tid; idx < 9216; idx += 384) {
        int pp  = (idx >= 4608);
        int id2 = idx - pp * 4608;
        int pos = pos0 + pp;
        int b = pos >> 6, hw = pos & 63, h = hw >> 3, w = hw & 7;
        int B_ = id2 >> 4, p = id2 & 15;
        int i = p >> 2, j = p & 3;       // ps = i*4 + j
        int Bcap = B_ / 9;
        int kk = B_ - Bcap * 9;
        int ki = kk / 3, kj = kk - ki * 3;
        int hh = 2 * h + ki - 1, ww = 2 * w + kj - 1;
        float val = 0.f;
        if ((unsigned)hh < 16u && (unsigned)ww < 16u)
            val = x[(((b * 32 + Bcap) * 16 + p) << 8) + (hh << 4) + ww];
        smem[pp * 4608 + (B_ << 4) + (j << 2) + i] = val;   // transposed store
    }
    __syncthreads();

    const ulonglong2* Xv0 = reinterpret_cast<const ulonglong2*>(Xs0);
    const ulonglong2* Xv1 = reinterpret_cast<const ulonglong2*>(Xs1);
    float4*       vbufv = reinterpret_cast<float4*>(vbuf);
    float4*       vcurv = reinterpret_cast<float4*>(vcur);
    ulonglong2*   vbufp = reinterpret_cast<ulonglong2*>(vbuf);
    const ulonglong2* vcurp = reinterpret_cast<const ulonglong2*>(vcur);

    u64 p00, p01, p02, p03, p04, p05, p06, p07;   // acc pos0
    u64 p10, p11, p12, p13, p14, p15, p16, p17;   // acc pos1

    const int VB1 = 1536;   // per-pos vbuf stride in float4/ulonglong2 units

    // ================= PASS A: norms (max-min) + uniform sums, both pos ===
    {
        float mx0 = -3.4e38f, mn0 = 3.4e38f, mx1 = -3.4e38f, mn1 = 3.4e38f;
        p00 = p01 = p02 = p03 = p04 = p05 = p06 = p07 = 0;
        p10 = p11 = p12 = p13 = p14 = p15 = p16 = p17 = 0;
        u64 w00, w01, w02, w03, w10, w11, w12, w13;
        u64 w20, w21, w22, w23, w30, w31, w32, w33;
        LOADW2(wp)
        for (int k = 0; k < NITER; k++) {
            int B  = wp + k * NW;
            int Bn = (k < NITER - 1) ? B + NW : wp;
            u64 ua0, ub0, ua1, ub1, ua2, ub2, ua3, ub3;
            u64 za0, zb0, za1, zb1, za2, zb2, za3, zb3;
            COMPUTE_U_I(Xv0, B, ua0, ub0, ua1, ub1, ua2, ub2, ua3, ub3)
            COMPUTE_U_I(Xv1, B, za0, zb0, za1, zb1, za2, zb2, za3, zb3)
            LOADW2(Bn)
            float s0, s1;
            PDOT8(s0, ua0, ub0, ua1, ub1, ua2, ub2, ua3, ub3,
                      ua0, ub0, ua1, ub1, ua2, ub2, ua3, ub3)
            PDOT8(s1, za0, zb0, za1, zb1, za2, zb2, za3, zb3,
                      za0, zb0, za1, zb1, za2, zb2, za3, zb3)
            float n0 = __fsqrt_rn(s0 + EPSF);
            float n1 = __fsqrt_rn(s1 + EPSF);
            mx0 = fmaxf(mx0, n0); mn0 = fminf(mn0, n0);
            mx1 = fmaxf(mx1, n1); mn1 = fminf(mn1, n1);
            ADD2(p00, p00, ua0); ADD2(p01, p01, ub0);
            ADD2(p02, p02, ua1); ADD2(p03, p03, ub1);
            ADD2(p04, p04, ua2); ADD2(p05, p05, ub2);
            ADD2(p06, p06, ua3); ADD2(p07, p07, ub3);
            ADD2(p10, p10, za0); ADD2(p11, p11, zb0);
            ADD2(p12, p12, za1); ADD2(p13, p13, zb1);
            ADD2(p14, p14, za2); ADD2(p15, p15, zb2);
            ADD2(p16, p16, za3); ADD2(p17, p17, zb3);
        }
        mred[(wp << 5) + lane]       = mx0;
        nred[(wp << 5) + lane]       = mn0;
        mred[384 + (wp << 5) + lane] = mx1;
        nred[384 + (wp << 5) + lane] = mn1;
        int base = ((wp << 5) + lane) << 2;
        ulonglong2 t;
        t.x = p00; t.y = p01; vbufp[base + 0] = t;
        t.x = p02; t.y = p03; vbufp[base + 1] = t;
        t.x = p04; t.y = p05; vbufp[base + 2] = t;
        t.x = p06; t.y = p07; vbufp[base + 3] = t;
        t.x = p10; t.y = p11; vbufp[VB1 + base + 0] = t;
        t.x = p12; t.y = p13; vbufp[VB1 + base + 1] = t;
        t.x = p14; t.y = p15; vbufp[VB1 + base + 2] = t;
        t.x = p16; t.y = p17; vbufp[VB1 + base + 3] = t;
    }
    __syncthreads();
    if (tid < 64) {
        int pp = tid >> 5, c = tid & 31;
        float M = -3.4e38f, m = 3.4e38f;
        #pragma unroll
        for (int k = 0; k < NW; k++) {
            M = fmaxf(M, mred[pp * 384 + (k << 5) + c]);
            m = fminf(m, nred[pp * 384 + (k << 5) + c]);
        }
        invd[(pp << 5) + c] = 1.f / (M - m);
    }
    __syncthreads();
    if (tid < 256) {
        int t = tid & 127, pp = tid >> 7;
        int C = t >> 2;
        int off = pp * VB1;
        float4 acc = vbufv[off + t];
        #pragma unroll
        for (int k = 1; k < NW; k++) {
            float4 u = vbufv[off + (k << 7) + t];
            acc.x += u.x; acc.y += u.y; acc.z += u.z; acc.w += u.w;
        }
        float f = invd[(pp << 5) + C] * (1.f / 32.f);
        acc.x *= f; acc.y *= f; acc.z *= f; acc.w *= f;
        float s = acc.x * acc.x + acc.y * acc.y + acc.z * acc.z + acc.w * acc.w;
        s += __shfl_xor_sync(0xffffffffu, s, 1);
        s += __shfl_xor_sync(0xffffffffu, s, 2);
        float nrm = __fsqrt_rn(s + EPSF);
        float g = 1.f / (1.f + nrm);
        acc.x *= g; acc.y *= g; acc.z *= g; acc.w *= g;
        vcurv[(pp << 7) + t] = acc;
    }
    __syncthreads();

    const float invd0 = invd[lane];
    const float invd1 = invd[32 + lane];

    u64 A0, A1, A2, A3, A4, A5, A6, A7;   // v (pos0), i-pair layout
    u64 B0, B1, B2, B3, B4, B5, B6, B7;   // v (pos1)
    {
        ulonglong2 t0 = vcurp[(lane << 2) + 0];
        ulonglong2 t1 = vcurp[(lane << 2) + 1];
        ulonglong2 t2 = vcurp[(lane << 2) + 2];
        ulonglong2 t3 = vcurp[(lane << 2) + 3];
        A0 = t0.x; A1 = t0.y; A2 = t1.x; A3 = t1.y;
        A4 = t2.x; A5 = t2.y; A6 = t3.x; A7 = t3.y;
        t0 = vcurp[128 + (lane << 2) + 0];
        t1 = vcurp[128 + (lane << 2) + 1];
        t2 = vcurp[128 + (lane << 2) + 2];
        t3 = vcurp[128 + (lane << 2) + 3];
        B0 = t0.x; B1 = t0.y; B2 = t1.x; B3 = t1.y;
        B4 = t2.x; B5 = t2.y; B6 = t3.x; B7 = t3.y;
    }

#define ROUTING_PASS_LOOP                                                      \
    {                                                                          \
        u64 w00, w01, w02, w03, w10, w11, w12, w13;                            \
        u64 w20, w21, w22, w23, w30, w31, w32, w33;                            \
        LOADW2(wp)                                                             \
        for (int k = 0; k < NITER; k++) {                                      \
            int B  = wp + k * NW;                                              \
            int Bn = (k < NITER - 1) ? B + NW : wp;                            \
            u64 ua0, ub0, ua1, ub1, ua2, ub2, ua3, ub3;                        \
            u64 za0, zb0, za1, zb1, za2, zb2, za3, zb3;                        \
            COMPUTE_U_I(Xv0, B, ua0, ub0, ua1, ub1, ua2, ub2, ua3, ub3)        \
            COMPUTE_U_I(Xv1, B, za0, zb0, za1, zb1, za2, zb2, za3, zb3)        \
            LOADW2(Bn)                                                         \
            float d0, d1;                                                      \
            PDOT8(d0, ua0, ub0, ua1, ub1, ua2, ub2, ua3, ub3,                  \
                      A0, A1, A2, A3, A4, A5, A6, A7)                          \
            PDOT8(d1, za0, zb0, za1, zb1, za2, zb2, za3, zb3,                  \
                      B0, B1, B2, B3, B4, B5, B6, B7)                          \
            float e0 = __expf(d0 * invd0);                                     \
            float e1 = __expf(d1 * invd1);                                     \
            float s0 = e0, s1 = e1;                                            \
            _Pragma("unroll")                                                  \
            for (int o = 16; o > 0; o >>= 1) {                                 \
                s0 += __shfl_xor_sync(0xffffffffu, s0, o);                     \
                s1 += __shfl_xor_sync(0xffffffffu, s1, o);                     \
            }                                                                  \
            float c0 = __fdividef(e0, s0);                                     \
            float c1 = __fdividef(e1, s1);                                     \
            u64 c0P, c1P;                                                      \
            PACK2(c0P, c0); PACK2(c1P, c1);                                    \
            FMA2(p00, c0P, ua0, p00); FMA2(p01, c0P, ub0, p01);                \
            FMA2(p02, c0P, ua1, p02); FMA2(p03, c0P, ub1, p03);                \
            FMA2(p04, c0P, ua2, p04); FMA2(p05, c0P, ub2, p05);                \
            FMA2(p06, c0P, ua3, p06); FMA2(p07, c0P, ub3, p07);                \
            FMA2(p10, c1P, za0, p10); FMA2(p11, c1P, zb0, p11);                \
            FMA2(p12, c1P, za1, p12); FMA2(p13, c1P, zb1, p13);                \
            FMA2(p14, c1P, za2, p14); FMA2(p15, c1P, zb2, p15);                \
            FMA2(p16, c1P, za3, p16); FMA2(p17, c1P, zb3, p17);                \
        }                                                                      \
    }

#define STORE_ACC                                                              \
    {                                                                          \
        int base = ((wp << 5) + lane) << 2;                                    \
        ulonglong2 t;                                                          \
        t.x = p00; t.y = p01; vbufp[base + 0] = t;                             \
        t.x = p02; t.y = p03; vbufp[base + 1] = t;                             \
        t.x = p04; t.y = p05; vbufp[base + 2] = t;                             \
        t.x = p06; t.y = p07; vbufp[base + 3] = t;                             \
        t.x = p10; t.y = p11; vbufp[VB1 + base + 0] = t;                       \
        t.x = p12; t.y = p13; vbufp[VB1 + base + 1] = t;                       \
        t.x = p14; t.y = p15; vbufp[VB1 + base + 2] = t;                       \
        t.x = p16; t.y = p17; vbufp[VB1 + base + 3] = t;                       \
    }

    // ================= PASS B: r1, c1, accumulate ========================
    {
        p00 = p01 = p02 = p03 = p04 = p05 = p06 = p07 = 0;
        p10 = p11 = p12 = p13 = p14 = p15 = p16 = p17 = 0;
        ROUTING_PASS_LOOP
        STORE_ACC
    }
    __syncthreads();
    if (tid < 256) {
        int t = tid & 127, pp = tid >> 7;
        int C = t >> 2;
        int off = pp * VB1;
        float4 acc = vbufv[off + t];
        #pragma unroll
        for (int k = 1; k < NW; k++) {
            float4 u = vbufv[off + (k << 7) + t];
            acc.x += u.x; acc.y += u.y; acc.z += u.z; acc.w += u.w;
        }
        float f = invd[(pp << 5) + C];
        acc.x *= f; acc.y *= f; acc.z *= f; acc.w *= f;
        float s = acc.x * acc.x + acc.y * acc.y + acc.z * acc.z + acc.w * acc.w;
        s += __shfl_xor_sync(0xffffffffu, s, 1);
        s += __shfl_xor_sync(0xffffffffu, s, 2);
        float nrm = __fsqrt_rn(s + EPSF);
        float g = 1.f / (1.f + nrm);
        acc.x *= g; acc.y *= g; acc.z *= g; acc.w *= g;
        vcurv[(pp << 7) + t] = acc;   // v1
    }
    __syncthreads();

    // v <- v0 + v1 per position (linearity of r)
    {
        ulonglong2 t0 = vcurp[(lane << 2) + 0];
        ulonglong2 t1 = vcurp[(lane << 2) + 1];
        ulonglong2 t2 = vcurp[(lane << 2) + 2];
        ulonglong2 t3 = vcurp[(lane << 2) + 3];
        ADD2(A0, A0, t0.x); ADD2(A1, A1, t0.y);
        ADD2(A2, A2, t1.x); ADD2(A3, A3, t1.y);
        ADD2(A4, A4, t2.x); ADD2(A5, A5, t2.y);
        ADD2(A6, A6, t3.x); ADD2(A7, A7, t3.y);
        t0 = vcurp[128 + (lane << 2) + 0];
        t1 = vcurp[128 + (lane << 2) + 1];
        t2 = vcurp[128 + (lane << 2) + 2];
        t3 = vcurp[128 + (lane << 2) + 3];
        ADD2(B0, B0, t0.x); ADD2(B1, B1, t0.y);
        ADD2(B2, B2, t1.x); ADD2(B3, B3, t1.y);
        ADD2(B4, B4, t2.x); ADD2(B5, B5, t2.y);
        ADD2(B6, B6, t3.x); ADD2(B7, B7, t3.y);
    }

    // ================= PASS C: r2, c2, accumulate, output ================
    {
        p00 = p01 = p02 = p03 = p04 = p05 = p06 = p07 = 0;
        p10 = p11 = p12 = p13 = p14 = p15 = p16 = p17 = 0;
        ROUTING_PASS_LOOP
        STORE_ACC
    }
    __syncthreads();
    if (tid < 256) {
        int t = tid & 127, pp = tid >> 7;
        int C = t >> 2, q = t & 3;
        int off = pp * VB1;
        float4 acc = vbufv[off + t];
        #pragma unroll
        for (int k = 1; k < NW; k++) {
            float4 u = vbufv[off + (k << 7) + t];
            acc.x += u.x; acc.y += u.y; acc.z += u.z; acc.w += u.w;
        }
        float f = invd[(pp << 5) + C];
        acc.x *= f; acc.y *= f; acc.z *= f; acc.w *= f;
        float s = acc.x * acc.x + acc.y * acc.y + acc.z * acc.z + acc.w * acc.w;
        s += __shfl_xor_sync(0xffffffffu, s, 1);
        s += __shfl_xor_sync(0xffffffffu, s, 2);
        float nrm = __fsqrt_rn(s + EPSF);
        float g = 1.f / (1.f + nrm);
        acc.x *= g; acc.y *= g; acc.z *= g; acc.w *= g;   // v2 (p_out)
        float s2 = acc.x * acc.x + acc.y * acc.y + acc.z * acc.z + acc.w * acc.w;
        s2 += __shfl_xor_sync(0xffffffffu, s2, 1);
        s2 += __shfl_xor_sync(0xffffffffu, s2, 2);
        float aout = __fsqrt_rn(s2 + EPSF);               // a_out = safe_norm(v2)
        // i-pair layout: quarter q holds ps = {q, q+4, q+8, q+12}
        int pos = pos0 + pp;
        int b = pos >> 6, hw = pos & 63;
        int basep = (((b * 32 + C) * 16 + q) << 6) + hw;
        out[basep]       = acc.x;
        out[basep + 256] = acc.y;
        out[basep + 512] = acc.z;
        out[basep + 768] = acc.w;
        if (q == 0)
            out[AOUT_BASE + ((b * 32 + C) << 6) + hw] = aout;
    }
}

extern "C" void kernel_launch(void* const* d_in, const int* in_sizes, int n_in,
                              void* d_out, int out_size) {
    (void)out_size;
    // Resolve inputs BY SIZE — immune to metadata ordering.
    const float* x  = nullptr;
    const float* Wg = nullptr;
    for (int i = 0; i < n_in; i++) {
        if (in_sizes[i] == 524288)      x  = (const float*)d_in[i];
        else if (in_sizes[i] == 147456) Wg = (const float*)d_in[i];
    }
    float* out = (float*)d_out;

    transpose_W_kernel<<<(288 * 16 * 32 + 255) / 256, 256>>>(Wg);

    const size_t smem_bytes = SMEM_FLOATS * sizeof(float);
    cudaFuncSetAttribute(convcaps_kernel,
                         cudaFuncAttributeMaxDynamicSharedMemorySize,
                         (int)smem_bytes);
    convcaps_kernel<<<128, 384, smem_bytes>>>(x, out);
}

// round 17
// speedup vs baseline: 1.0353x; 1.0353x over previous
#include <cuda_runtime.h>
#include <math.h>

#define EPSF 1e-5f
#define NW 16            // warps per CTA
#define NITER 18         // 288 / NW

// Re-laid-out weights: Wt4[B][g][C] (float4), g = jk/4.
__device__ float4 Wt4_buf[288 * 4 * 32];

__global__ void transpose_W_kernel(const float* __restrict__ Wg) {
    int idx = blockIdx.x * 256 + threadIdx.x;
    if (idx >= 288 * 16 * 32) return;
    int q = idx & 3;
    int C = (idx >> 2) & 31;
    int g = (idx >> 7) & 3;
    int B = idx >> 9;
    ((float*)Wt4_buf)[idx] = Wg[((B << 5) + C) * 16 + (g << 2) + q];
}

typedef unsigned long long u64;

// packed f32x2 helpers
#define PACK2(d, s)      asm("mov.b64 %0, {%1, %1};" : "=l"(d) : "f"(s))
#define UNPK2(lo, hi, s) asm("mov.b64 {%0, %1}, %2;" : "=f"(lo), "=f"(hi) : "l"(s))
#define FMA2(d, a, b, c) asm("fma.rn.f32x2 %0, %1, %2, %3;" : "=l"(d) : "l"(a), "l"(b), "l"(c))
#define MUL2(d, a, b)    asm("mul.rn.f32x2 %0, %1, %2;" : "=l"(d) : "l"(a), "l"(b))
#define ADD2(d, a, b)    asm("add.rn.f32x2 %0, %1, %2;" : "=l"(d) : "l"(a), "l"(b))

// SMEM layout (floats) — TWO positions per CTA, 16 warps:
//  Xs0  [288*16]        = 4608   @0
//  Xs1  [288*16]        = 4608   @4608
//  vbuf [2][16*32*16]   = 16384  @9216
//  vcur [2][32*16]      = 1024   @25600
//  invd [2][32]         = 64     @26624
//  mred [2][16*32]      = 1024   @26688
//  nred [2][16*32]      = 1024   @27712
#define SMEM_FLOATS 28736

// p_out has 4*32*16*8*8 = 131072 elements; a_out follows it.
#define AOUT_BASE 131072

#define LOADW(B, wa0, wb0, wa1, wb1, wa2, wb2, wa3, wb3)                       \
    {                                                                          \
        const ulonglong2* Wp_ =                                                \
            reinterpret_cast<const ulonglong2*>(Wt4_buf) + ((B) << 7) + lane;  \
        ulonglong2 t0 = Wp_[0], t1 = Wp_[32], t2 = Wp_[64], t3 = Wp_[96];      \
        wa0 = t0.x; wb0 = t0.y; wa1 = t1.x; wb1 = t1.y;                        \
        wa2 = t2.x; wb2 = t2.y; wa3 = t3.x; wb3 = t3.y;                        \
    }

// u[16] = X[B] (4x4) @ W (packed regs). XV = float4 view of a position's Xs.
#define COMPUTE_U_P(XV, B, ua0, ub0, ua1, ub1, ua2, ub2, ua3, ub3)             \
    {                                                                          \
        const float4* Xp = (XV) + ((B) << 2);                                  \
        float4 xr0 = Xp[0], xr1 = Xp[1], xr2 = Xp[2], xr3 = Xp[3];             \
        u64 xp0, xp1, xp2, xp3;                                                \
        PACK2(xp0, xr0.x); PACK2(xp1, xr0.y); PACK2(xp2, xr0.z); PACK2(xp3, xr0.w); \
        MUL2(ua0, xp0, wa0); MUL2(ub0, xp0, wb0);                              \
        FMA2(ua0, xp1, wa1, ua0); FMA2(ub0, xp1, wb1, ub0);                    \
        FMA2(ua0, xp2, wa2, ua0); FMA2(ub0, xp2, wb2, ub0);                    \
        FMA2(ua0, xp3, wa3, ua0); FMA2(ub0, xp3, wb3, ub0);                    \
        PACK2(xp0, xr1.x); PACK2(xp1, xr1.y); PACK2(xp2, xr1.z); PACK2(xp3, xr1.w); \
        MUL2(ua1, xp0, wa0); MUL2(ub1, xp0, wb0);                              \
        FMA2(ua1, xp1, wa1, ua1); FMA2(ub1, xp1, wb1, ub1);                    \
        FMA2(ua1, xp2, wa2, ua1); FMA2(ub1, xp2, wb2, ub1);                    \
        FMA2(ua1, xp3, wa3, ua1); FMA2(ub1, xp3, wb3, ub1);                    \
        PACK2(xp0, xr2.x); PACK2(xp1, xr2.y); PACK2(xp2, xr2.z); PACK2(xp3, xr2.w); \
        MUL2(ua2, xp0, wa0); MUL2(ub2, xp0, wb0);                              \
        FMA2(ua2, xp1, wa1, ua2); FMA2(ub2, xp1, wb1, ub2);                    \
        FMA2(ua2, xp2, wa2, ua2); FMA2(ub2, xp2, wb2, ub2);                    \
        FMA2(ua2, xp3, wa3, ua2); FMA2(ub2, xp3, wb3, ub2);                    \
        PACK2(xp0, xr3.x); PACK2(xp1, xr3.y); PACK2(xp2, xr3.z); PACK2(xp3, xr3.w); \
        MUL2(ua3, xp0, wa0); MUL2(ub3, xp0, wb0);                              \
        FMA2(ua3, xp1, wa1, ua3); FMA2(ub3, xp1, wb1, ub3);                    \
        FMA2(ua3, xp2, wa2, ua3); FMA2(ub3, xp2, wb2, ub3);                    \
        FMA2(ua3, xp3, wa3, ua3); FMA2(ub3, xp3, wb3, ub3);                    \
    }

// packed elementwise dot of 8 pairs -> scalar (lo+hi)
#define PDOT8(res, ua0, ub0, ua1, ub1, ua2, ub2, ua3, ub3,                     \
              va0, vb0, va1, vb1, va2, vb2, va3, vb3)                          \
    {                                                                          \
        u64 t_;                                                                \
        MUL2(t_, ua0, va0); FMA2(t_, ub0, vb0, t_);                            \
        FMA2(t_, ua1, va1, t_); FMA2(t_, ub1, vb1, t_);                        \
        FMA2(t_, ua2, va2, t_); FMA2(t_, ub2, vb2, t_);                        \
        FMA2(t_, ua3, va3, t_); FMA2(t_, ub3, vb3, t_);                        \
        float lo_, hi_;                                                        \
        UNPK2(lo_, hi_, t_);                                                   \
        res = lo_ + hi_;                                                       \
    }

__global__ __launch_bounds__(512, 1)
void convcaps_kernel(const float* __restrict__ x,
                     float* __restrict__ out) {
    extern __shared__ float smem[];
    float* Xs0  = smem;
    float* Xs1  = smem + 4608;
    float* vbuf = smem + 9216;
    float* vcur = smem + 25600;
    float* invd = smem + 26624;
    float* mred = smem + 26688;
    float* nred = smem + 27712;

    const int tid  = threadIdx.x;
    const int lane = tid & 31;       // = C
    const int wp   = tid >> 5;       // warp id 0..15, B ≡ wp (mod 16)
    const int pos0 = blockIdx.x * 2; // two positions per CTA

    // ---- gather patch poses for BOTH positions ----
    for (int idx = tid; idx < 9216; idx += 512) {
        int pp  = (idx >= 4608);
        int id2 = idx - pp * 4608;
        int pos = pos0 + pp;
        int b = pos >> 6, hw = pos & 63, h = hw >> 3, w = hw & 7;
        int B_ = id2 >> 4, p = id2 & 15;
        int Bcap = B_ / 9;
        int kk = B_ - Bcap * 9;
        int ki = kk / 3, kj = kk - ki * 3;
        int hh = 2 * h + ki - 1, ww = 2 * w + kj - 1;
        float val = 0.f;
        if ((unsigned)hh < 16u && (unsigned)ww < 16u)
            val = x[(((b * 32 + Bcap) * 16 + p) << 8) + (hh << 4) + ww];
        smem[idx] = val;
    }
    __syncthreads();

    const float4* Xv0 = reinterpret_cast<const float4*>(Xs0);
    const float4* Xv1 = reinterpret_cast<const float4*>(Xs1);
    float4*       vbufv = reinterpret_cast<float4*>(vbuf);
    float4*       vcurv = reinterpret_cast<float4*>(vcur);
    ulonglong2*   vbufp = reinterpret_cast<ulonglong2*>(vbuf);
    const ulonglong2* vcurp = reinterpret_cast<const ulonglong2*>(vcur);

    u64 p00, p01, p02, p03, p04, p05, p06, p07;   // acc pos0
    u64 p10, p11, p12, p13, p14, p15, p16, p17;   // acc pos1

    // per-pos vbuf stride: 16*32*16 floats = 2048 float4/ulonglong2
    const int VB1 = 2048;

    // ================= PASS A: norms (max-min) + uniform sums, both pos ===
    {
        float mx0 = -3.4e38f, mn0 = 3.4e38f, mx1 = -3.4e38f, mn1 = 3.4e38f;
        p00 = p01 = p02 = p03 = p04 = p05 = p06 = p07 = 0;
        p10 = p11 = p12 = p13 = p14 = p15 = p16 = p17 = 0;
        u64 wa0, wb0, wa1, wb1, wa2, wb2, wa3, wb3;
        LOADW(wp, wa0, wb0, wa1, wb1, wa2, wb2, wa3, wb3)
        for (int k = 0; k < NITER; k++) {
            int B  = wp + k * NW;
            int Bn = (k < NITER - 1) ? B + NW : wp;
            u64 ua0, ub0, ua1, ub1, ua2, ub2, ua3, ub3;
            u64 za0, zb0, za1, zb1, za2, zb2, za3, zb3;
            COMPUTE_U_P(Xv0, B, ua0, ub0, ua1, ub1, ua2, ub2, ua3, ub3)
            COMPUTE_U_P(Xv1, B, za0, zb0, za1, zb1, za2, zb2, za3, zb3)
            LOADW(Bn, wa0, wb0, wa1, wb1, wa2, wb2, wa3, wb3)
            float s0, s1;
            PDOT8(s0, ua0, ub0, ua1, ub1, ua2, ub2, ua3, ub3,
                      ua0, ub0, ua1, ub1, ua2, ub2, ua3, ub3)
            PDOT8(s1, za0, zb0, za1, zb1, za2, zb2, za3, zb3,
                      za0, zb0, za1, zb1, za2, zb2, za3, zb3)
            float n0 = __fsqrt_rn(s0 + EPSF);
            float n1 = __fsqrt_rn(s1 + EPSF);
            mx0 = fmaxf(mx0, n0); mn0 = fminf(mn0, n0);
            mx1 = fmaxf(mx1, n1); mn1 = fminf(mn1, n1);
            ADD2(p00, p00, ua0); ADD2(p01, p01, ub0);
            ADD2(p02, p02, ua1); ADD2(p03, p03, ub1);
            ADD2(p04, p04, ua2); ADD2(p05, p05, ub2);
            ADD2(p06, p06, ua3); ADD2(p07, p07, ub3);
            ADD2(p10, p10, za0); ADD2(p11, p11, zb0);
            ADD2(p12, p12, za1); ADD2(p13, p13, zb1);
            ADD2(p14, p14, za2); ADD2(p15, p15, zb2);
            ADD2(p16, p16, za3); ADD2(p17, p17, zb3);
        }
        mred[(wp << 5) + lane]       = mx0;
        nred[(wp << 5) + lane]       = mn0;
        mred[512 + (wp << 5) + lane] = mx1;
        nred[512 + (wp << 5) + lane] = mn1;
        int base = ((wp << 5) + lane) << 2;
        ulonglong2 t;
        t.x = p00; t.y = p01; vbufp[base + 0] = t;
        t.x = p02; t.y = p03; vbufp[base + 1] = t;
        t.x = p04; t.y = p05; vbufp[base + 2] = t;
        t.x = p06; t.y = p07; vbufp[base + 3] = t;
        t.x = p10; t.y = p11; vbufp[VB1 + base + 0] = t;
        t.x = p12; t.y = p13; vbufp[VB1 + base + 1] = t;
        t.x = p14; t.y = p15; vbufp[VB1 + base + 2] = t;
        t.x = p16; t.y = p17; vbufp[VB1 + base + 3] = t;
    }
    __syncthreads();
    if (tid < 64) {
        int pp = tid >> 5, c = tid & 31;
        float M = -3.4e38f, m = 3.4e38f;
        #pragma unroll
        for (int k = 0; k < NW; k++) {
            M = fmaxf(M, mred[pp * 512 + (k << 5) + c]);
            m = fminf(m, nred[pp * 512 + (k << 5) + c]);
        }
        invd[(pp << 5) + c] = 1.f / (M - m);
    }
    __syncthreads();
    // reduce across warps + squash -> v0 for both positions (256 threads)
    if (tid < 256) {
        int t = tid & 127, pp = tid >> 7;
        int C = t >> 2;
        int off = pp * VB1;
        float4 acc = vbufv[off + t];
        #pragma unroll
        for (int k = 1; k < NW; k++) {
            float4 u = vbufv[off + (k << 7) + t];
            acc.x += u.x; acc.y += u.y; acc.z += u.z; acc.w += u.w;
        }
        float f = invd[(pp << 5) + C] * (1.f / 32.f);
        acc.x *= f; acc.y *= f; acc.z *= f; acc.w *= f;
        float s = acc.x * acc.x + acc.y * acc.y + acc.z * acc.z + acc.w * acc.w;
        s += __shfl_xor_sync(0xffffffffu, s, 1);
        s += __shfl_xor_sync(0xffffffffu, s, 2);
        float nrm = __fsqrt_rn(s + EPSF);
        float g = 1.f / (1.f + nrm);
        acc.x *= g; acc.y *= g; acc.z *= g; acc.w *= g;
        vcurv[(pp << 7) + t] = acc;
    }
    __syncthreads();

    const float invd0 = invd[lane];
    const float invd1 = invd[32 + lane];

    // v0 packed per position, kept in registers
    u64 A0, A1, A2, A3, A4, A5, A6, A7;   // v (pos0)
    u64 B0, B1, B2, B3, B4, B5, B6, B7;   // v (pos1)
    {
        ulonglong2 t0 = vcurp[(lane << 2) + 0];
        ulonglong2 t1 = vcurp[(lane << 2) + 1];
        ulonglong2 t2 = vcurp[(lane << 2) + 2];
        ulonglong2 t3 = vcurp[(lane << 2) + 3];
        A0 = t0.x; A1 = t0.y; A2 = t1.x; A3 = t1.y;
        A4 = t2.x; A5 = t2.y; A6 = t3.x; A7 = t3.y;
        t0 = vcurp[128 + (lane << 2) + 0];
        t1 = vcurp[128 + (lane << 2) + 1];
        t2 = vcurp[128 + (lane << 2) + 2];
        t3 = vcurp[128 + (lane << 2) + 3];
        B0 = t0.x; B1 = t0.y; B2 = t1.x; B3 = t1.y;
        B4 = t2.x; B5 = t2.y; B6 = t3.x; B7 = t3.y;
    }

// Routing pass: one W load feeds both positions; twin shuffle chains.
#define ROUTING_PASS_LOOP                                                      \
    {                                                                          \
        u64 wa0, wb0, wa1, wb1, wa2, wb2, wa3, wb3;                            \
        LOADW(wp, wa0, wb0, wa1, wb1, wa2, wb2, wa3, wb3)                      \
        for (int k = 0; k < NITER; k++) {                                      \
            int B  = wp + k * NW;                                              \
            int Bn = (k < NITER - 1) ? B + NW : wp;                            \
            u64 ua0, ub0, ua1, ub1, ua2, ub2, ua3, ub3;                        \
            u64 za0, zb0, za1, zb1, za2, zb2, za3, zb3;                        \
            COMPUTE_U_P(Xv0, B, ua0, ub0, ua1, ub1, ua2, ub2, ua3, ub3)        \
            COMPUTE_U_P(Xv1, B, za0, zb0, za1, zb1, za2, zb2, za3, zb3)        \
            LOADW(Bn, wa0, wb0, wa1, wb1, wa2, wb2, wa3, wb3)                  \
            float d0, d1;                                                      \
            PDOT8(d0, ua0, ub0, ua1, ub1, ua2, ub2, ua3, ub3,                  \
                      A0, A1, A2, A3, A4, A5, A6, A7)                          \
            PDOT8(d1, za0, zb0, za1, zb1, za2, zb2, za3, zb3,                  \
                      B0, B1, B2, B3, B4, B5, B6, B7)                          \
            float e0 = __expf(d0 * invd0);                                     \
            float e1 = __expf(d1 * invd1);                                     \
            float s0 = e0, s1 = e1;                                            \
            _Pragma("unroll")                                                  \
            for (int o = 16; o > 0; o >>= 1) {                                 \
                s0 += __shfl_xor_sync(0xffffffffu, s0, o);                     \
                s1 += __shfl_xor_sync(0xffffffffu, s1, o);                     \
            }                                                                  \
            float c0 = __fdividef(e0, s0);                                     \
            float c1 = __fdividef(e1, s1);                                     \
            u64 c0P, c1P;                                                      \
            PACK2(c0P, c0); PACK2(c1P, c1);                                    \
            FMA2(p00, c0P, ua0, p00); FMA2(p01, c0P, ub0, p01);                \
            FMA2(p02, c0P, ua1, p02); FMA2(p03, c0P, ub1, p03);                \
            FMA2(p04, c0P, ua2, p04); FMA2(p05, c0P, ub2, p05);                \
            FMA2(p06, c0P, ua3, p06); FMA2(p07, c0P, ub3, p07);                \
            FMA2(p10, c1P, za0, p10); FMA2(p11, c1P, zb0, p11);                \
            FMA2(p12, c1P, za1, p12); FMA2(p13, c1P, zb1, p13);                \
            FMA2(p14, c1P, za2, p14); FMA2(p15, c1P, zb2, p15);                \
            FMA2(p16, c1P, za3, p16); FMA2(p17, c1P, zb3, p17);                \
        }                                                                      \
    }

#define STORE_ACC                                                              \
    {                                                                          \
        int base = ((wp << 5) + lane) << 2;                                    \
        ulonglong2 t;                                                          \
        t.x = p00; t.y = p01; vbufp[base + 0] = t;                             \
        t.x = p02; t.y = p03; vbufp[base + 1] = t;                             \
        t.x = p04; t.y = p05; vbufp[base + 2] = t;                             \
        t.x = p06; t.y = p07; vbufp[base + 3] = t;                             \
        t.x = p10; t.y = p11; vbufp[VB1 + base + 0] = t;                       \
        t.x = p12; t.y = p13; vbufp[VB1 + base + 1] = t;                       \
        t.x = p14; t.y = p15; vbufp[VB1 + base + 2] = t;                       \
        t.x = p16; t.y = p17; vbufp[VB1 + base + 3] = t;                       \
    }

    // ================= PASS B: r1, c1, accumulate ========================
    {
        p00 = p01 = p02 = p03 = p04 = p05 = p06 = p07 = 0;
        p10 = p11 = p12 = p13 = p14 = p15 = p16 = p17 = 0;
        ROUTING_PASS_LOOP
        STORE_ACC
    }
    __syncthreads();
    if (tid < 256) {
        int t = tid & 127, pp = tid >> 7;
        int C = t >> 2;
        int off = pp * VB1;
        float4 acc = vbufv[off + t];
        #pragma unroll
        for (int k = 1; k < NW; k++) {
            float4 u = vbufv[off + (k << 7) + t];
            acc.x += u.x; acc.y += u.y; acc.z += u.z; acc.w += u.w;
        }
        float f = invd[(pp << 5) + C];
        acc.x *= f; acc.y *= f; acc.z *= f; acc.w *= f;
        float s = acc.x * acc.x + acc.y * acc.y + acc.z * acc.z + acc.w * acc.w;
        s += __shfl_xor_sync(0xffffffffu, s, 1);
        s += __shfl_xor_sync(0xffffffffu, s, 2);
        float nrm = __fsqrt_rn(s + EPSF);
        float g = 1.f / (1.f + nrm);
        acc.x *= g; acc.y *= g; acc.z *= g; acc.w *= g;
        vcurv[(pp << 7) + t] = acc;   // v1
    }
    __syncthreads();

    // v <- v0 + v1 per position (linearity of r)
    {
        ulonglong2 t0 = vcurp[(lane << 2) + 0];
        ulonglong2 t1 = vcurp[(lane << 2) + 1];
        ulonglong2 t2 = vcurp[(lane << 2) + 2];
        ulonglong2 t3 = vcurp[(lane << 2) + 3];
        ADD2(A0, A0, t0.x); ADD2(A1, A1, t0.y);
        ADD2(A2, A2, t1.x); ADD2(A3, A3, t1.y);
        ADD2(A4, A4, t2.x); ADD2(A5, A5, t2.y);
        ADD2(A6, A6, t3.x); ADD2(A7, A7, t3.y);
        t0 = vcurp[128 + (lane << 2) + 0];
        t1 = vcurp[128 + (lane << 2) + 1];
        t2 = vcurp[128 + (lane << 2) + 2];
        t3 = vcurp[128 + (lane << 2) + 3];
        ADD2(B0, B0, t0.x); ADD2(B1, B1, t0.y);
        ADD2(B2, B2, t1.x); ADD2(B3, B3, t1.y);
        ADD2(B4, B4, t2.x); ADD2(B5, B5, t2.y);
        ADD2(B6, B6, t3.x); ADD2(B7, B7, t3.y);
    }

    // ================= PASS C: r2, c2, accumulate, output ================
    {
        p00 = p01 = p02 = p03 = p04 = p05 = p06 = p07 = 0;
        p10 = p11 = p12 = p13 = p14 = p15 = p16 = p17 = 0;
        ROUTING_PASS_LOOP
        STORE_ACC
    }
    __syncthreads();
    if (tid < 256) {
        int t = tid & 127, pp = tid >> 7;
        int C = t >> 2, q = t & 3;
        int off = pp * VB1;
        float4 acc = vbufv[off + t];
        #pragma unroll
        for (int k = 1; k < NW; k++) {
            float4 u = vbufv[off + (k << 7) + t];
            acc.x += u.x; acc.y += u.y; acc.z += u.z; acc.w += u.w;
        }
        float f = invd[(pp << 5) + C];
        acc.x *= f; acc.y *= f; acc.z *= f; acc.w *= f;
        float s = acc.x * acc.x + acc.y * acc.y + acc.z * acc.z + acc.w * acc.w;
        s += __shfl_xor_sync(0xffffffffu, s, 1);
        s += __shfl_xor_sync(0xffffffffu, s, 2);
        float nrm = __fsqrt_rn(s + EPSF);
        float g = 1.f / (1.f + nrm);
        acc.x *= g; acc.y *= g; acc.z *= g; acc.w *= g;   // v2 (p_out)
        float s2 = acc.x * acc.x + acc.y * acc.y + acc.z * acc.z + acc.w * acc.w;
        s2 += __shfl_xor_sync(0xffffffffu, s2, 1);
        s2 += __shfl_xor_sync(0xffffffffu, s2, 2);
        float aout = __fsqrt_rn(s2 + EPSF);               // a_out = safe_norm(v2)
        int pos = pos0 + pp;
        int b = pos >> 6, hw = pos & 63;
        int basep = (((b * 32 + C) * 16 + (q << 2)) << 6) + hw;
        out[basep]       = acc.x;
        out[basep + 64]  = acc.y;
        out[basep + 128] = acc.z;
        out[basep + 192] = acc.w;
        if (q == 0)
            out[AOUT_BASE + ((b * 32 + C) << 6) + hw] = aout;
    }
}

extern "C" void kernel_launch(void* const* d_in, const int* in_sizes, int n_in,
                              void* d_out, int out_size) {
    (void)out_size;
    // Resolve inputs BY SIZE — immune to metadata ordering.
    const float* x  = nullptr;
    const float* Wg = nullptr;
    for (int i = 0; i < n_in; i++) {
        if (in_sizes[i] == 524288)      x  = (const float*)d_in[i];
        else if (in_sizes[i] == 147456) Wg = (const float*)d_in[i];
    }
    float* out = (float*)d_out;

    transpose_W_kernel<<<(288 * 16 * 32 + 255) / 256, 256>>>(Wg);

    const size_t smem_bytes = SMEM_FLOATS * sizeof(float);
    cudaFuncSetAttribute(convcaps_kernel,
                         cudaFuncAttributeMaxDynamicSharedMemorySize,
                         (int)smem_bytes);
    convcaps_kernel<<<128, 512, smem_bytes>>>(x, out);
}